// round 1
// baseline (speedup 1.0000x reference)
#include <cuda_runtime.h>
#include <cuda_bf16.h>

#define HH   1024
#define WW   1024
#define RAD  40
#define EPSF 1e-3f
#define MAXIMG 12
#define HWSZ (HH * WW)
#define SEG  64          // rows per thread in vertical sliding pass

// ---------------------------------------------------------------------------
// Scratch (static __device__ arrays -- no runtime allocation).
//   g_s0..g_s3 : row-boxsums of I, p, I*p, I*I   (stage 1)
//                reused as row-boxsums of a, b   (stage 2: s0, s1)
//   g_a, g_b   : per-pixel a, b
// ---------------------------------------------------------------------------
__device__ float g_s0[MAXIMG * HWSZ];
__device__ float g_s1[MAXIMG * HWSZ];
__device__ float g_s2[MAXIMG * HWSZ];
__device__ float g_s3[MAXIMG * HWSZ];
__device__ float g_a [MAXIMG * HWSZ];
__device__ float g_b [MAXIMG * HWSZ];

// ---------------------------------------------------------------------------
// Row box-sum via per-row prefix sum in shared memory.
// Block = 256 threads, each owns 4 consecutive elements of a 1024-wide row.
// csp[x] = sum of elements [0, x), length WW+1.
// Returns the 4 box sums for this thread's elements.
// ---------------------------------------------------------------------------
__device__ __forceinline__ float4 scan_box(float4 e, float* csp, float* wsum, int t)
{
    float s0 = e.x;
    float s1 = s0 + e.y;
    float s2 = s1 + e.z;
    float s3 = s2 + e.w;          // thread-local inclusive sums

    int lane = t & 31;
    int warp = t >> 5;

    // inclusive warp scan of per-thread totals
    float v = s3;
#pragma unroll
    for (int off = 1; off < 32; off <<= 1) {
        float n = __shfl_up_sync(0xffffffffu, v, off);
        if (lane >= off) v += n;
    }
    if (lane == 31) wsum[warp] = v;
    __syncthreads();

    float wb = 0.0f;
#pragma unroll
    for (int w2 = 0; w2 < 7; w2++)
        wb += (w2 < warp) ? wsum[w2] : 0.0f;

    float excl = wb + v - s3;     // sum of all elements before index 4t

    int x = t * 4;
    csp[x + 0] = excl;
    csp[x + 1] = excl + s0;
    csp[x + 2] = excl + s1;
    csp[x + 3] = excl + s2;
    if (t == 255) csp[WW] = excl + s3;
    __syncthreads();

    float4 o;
    {
        int x0 = x;
        o.x = csp[min(x0 + RAD + 1, WW)] - csp[max(x0 - RAD, 0)];
        o.y = csp[min(x0 + RAD + 2, WW)] - csp[max(x0 + 1 - RAD, 0)];
        o.z = csp[min(x0 + RAD + 3, WW)] - csp[max(x0 + 2 - RAD, 0)];
        o.w = csp[min(x0 + RAD + 4, WW)] - csp[max(x0 + 3 - RAD, 0)];
    }
    __syncthreads();              // csp / wsum safe for reuse
    return o;
}

// ---------------------------------------------------------------------------
// Stage 1 horizontal: read I, p; write row-boxsums of I, p, I*p, I*I
// grid = (HH, nimg), block = 256
// ---------------------------------------------------------------------------
__global__ __launch_bounds__(256)
void hpass1(const float* __restrict__ I, const float* __restrict__ P)
{
    __shared__ float csp[WW + 1];
    __shared__ float wsum[8];

    int t = threadIdx.x;
    size_t base = ((size_t)blockIdx.y * HH + blockIdx.x) * WW;
    size_t off  = base + (size_t)t * 4;

    float4 vI = *(const float4*)(I + off);
    float4 vP = *(const float4*)(P + off);

    float4 o;
    o = scan_box(vI, csp, wsum, t);
    *(float4*)(g_s0 + off) = o;

    o = scan_box(vP, csp, wsum, t);
    *(float4*)(g_s1 + off) = o;

    float4 ip = make_float4(vI.x * vP.x, vI.y * vP.y, vI.z * vP.z, vI.w * vP.w);
    o = scan_box(ip, csp, wsum, t);
    *(float4*)(g_s2 + off) = o;

    float4 ii = make_float4(vI.x * vI.x, vI.y * vI.y, vI.z * vI.z, vI.w * vI.w);
    o = scan_box(ii, csp, wsum, t);
    *(float4*)(g_s3 + off) = o;
}

// ---------------------------------------------------------------------------
// Stage 1 vertical: sliding-window column sums of the 4 planes,
// fused a/b computation.  grid = (WW/256, HH/SEG, nimg), block = 256
// ---------------------------------------------------------------------------
__global__ __launch_bounds__(256)
void vpass1()
{
    int col = blockIdx.x * 256 + threadIdx.x;
    int y0  = blockIdx.y * SEG;
    size_t base = (size_t)blockIdx.z * HWSZ + col;

    const float* s0 = g_s0 + base;
    const float* s1 = g_s1 + base;
    const float* s2 = g_s2 + base;
    const float* s3 = g_s3 + base;

    float a0 = 0.f, a1 = 0.f, a2 = 0.f, a3 = 0.f;
    int ys = max(y0 - RAD, 0);
    int ye = min(y0 + RAD, HH - 1);
    for (int y = ys; y <= ye; y++) {
        size_t o = (size_t)y * WW;
        a0 += s0[o]; a1 += s1[o]; a2 += s2[o]; a3 += s3[o];
    }

    float cx = (float)(min(col + RAD, WW - 1) - max(col - RAD, 0) + 1);

    for (int y = y0; y < y0 + SEG; y++) {
        float cy  = (float)(min(y + RAD, HH - 1) - max(y - RAD, 0) + 1);
        float inv = 1.0f / (cx * cy);

        float mI  = a0 * inv;
        float mP  = a1 * inv;
        float mIP = a2 * inv;
        float mII = a3 * inv;

        float cov = mIP - mI * mP;
        float var = mII - mI * mI;
        float a   = cov / (var + EPSF);
        float b   = mP - a * mI;

        size_t o = (size_t)y * WW;
        g_a[base + o] = a;
        g_b[base + o] = b;

        int yadd = y + RAD + 1;
        if (yadd < HH) {
            size_t oo = (size_t)yadd * WW;
            a0 += s0[oo]; a1 += s1[oo]; a2 += s2[oo]; a3 += s3[oo];
        }
        int ysub = y - RAD;
        if (ysub >= 0) {
            size_t oo = (size_t)ysub * WW;
            a0 -= s0[oo]; a1 -= s1[oo]; a2 -= s2[oo]; a3 -= s3[oo];
        }
    }
}

// ---------------------------------------------------------------------------
// Stage 2 horizontal: row-boxsums of a, b -> g_s0, g_s1 (reuse)
// grid = (HH, nimg), block = 256
// ---------------------------------------------------------------------------
__global__ __launch_bounds__(256)
void hpass2()
{
    __shared__ float csp[WW + 1];
    __shared__ float wsum[8];

    int t = threadIdx.x;
    size_t base = ((size_t)blockIdx.y * HH + blockIdx.x) * WW;
    size_t off  = base + (size_t)t * 4;

    float4 va = *(const float4*)(g_a + off);
    float4 vb = *(const float4*)(g_b + off);

    float4 o;
    o = scan_box(va, csp, wsum, t);
    *(float4*)(g_s0 + off) = o;

    o = scan_box(vb, csp, wsum, t);
    *(float4*)(g_s1 + off) = o;
}

// ---------------------------------------------------------------------------
// Stage 2 vertical: sliding-window column sums of a, b; final output.
// out = mean_a * I + mean_b
// grid = (WW/256, HH/SEG, nimg), block = 256
// ---------------------------------------------------------------------------
__global__ __launch_bounds__(256)
void vpass2(const float* __restrict__ I, float* __restrict__ out)
{
    int col = blockIdx.x * 256 + threadIdx.x;
    int y0  = blockIdx.y * SEG;
    size_t base = (size_t)blockIdx.z * HWSZ + col;

    const float* s0 = g_s0 + base;
    const float* s1 = g_s1 + base;

    float a0 = 0.f, a1 = 0.f;
    int ys = max(y0 - RAD, 0);
    int ye = min(y0 + RAD, HH - 1);
    for (int y = ys; y <= ye; y++) {
        size_t o = (size_t)y * WW;
        a0 += s0[o]; a1 += s1[o];
    }

    float cx = (float)(min(col + RAD, WW - 1) - max(col - RAD, 0) + 1);

    for (int y = y0; y < y0 + SEG; y++) {
        float cy  = (float)(min(y + RAD, HH - 1) - max(y - RAD, 0) + 1);
        float inv = 1.0f / (cx * cy);

        size_t o = (size_t)y * WW;
        float iv = I[base + o];
        out[base + o] = (a0 * inv) * iv + (a1 * inv);

        int yadd = y + RAD + 1;
        if (yadd < HH) {
            size_t oo = (size_t)yadd * WW;
            a0 += s0[oo]; a1 += s1[oo];
        }
        int ysub = y - RAD;
        if (ysub >= 0) {
            size_t oo = (size_t)ysub * WW;
            a0 -= s0[oo]; a1 -= s1[oo];
        }
    }
}

// ---------------------------------------------------------------------------
extern "C" void kernel_launch(void* const* d_in, const int* in_sizes, int n_in,
                              void* d_out, int out_size)
{
    const float* I = (const float*)d_in[0];
    const float* P = (const float*)d_in[1];
    float* out     = (float*)d_out;

    int nimg = in_sizes[0] / HWSZ;      // B*C images of 1024x1024
    if (nimg > MAXIMG) nimg = MAXIMG;

    dim3 hgrid(HH, nimg);
    dim3 vgrid(WW / 256, HH / SEG, nimg);

    hpass1<<<hgrid, 256>>>(I, P);
    vpass1<<<vgrid, 256>>>();
    hpass2<<<hgrid, 256>>>();
    vpass2<<<vgrid, 256>>>(I, out);
}

// round 2
// speedup vs baseline: 1.2908x; 1.2908x over previous
#include <cuda_runtime.h>
#include <cuda_bf16.h>

#define HH   1024
#define WW   1024
#define RAD  40
#define EPSF 1e-3f
#define MAXIMG 12
#define HWSZ (HH * WW)
#define SEG  128         // rows per thread in vertical sliding passes
#define UNR1 4           // unroll (rows prefetched) in vpass1
#define UNR2 8           // unroll in vpass2

// ---------------------------------------------------------------------------
// Scratch (static __device__ arrays -- no runtime allocation).
//   g_S4  : interleaved row-boxsums of (I, p, I*p, I*I)  -- float4 per pixel
//   g_ab  : interleaved (a, b)                           -- float2 per pixel
//   g_sab : interleaved row-boxsums of (a, b)            -- float2 per pixel
// ---------------------------------------------------------------------------
__device__ float4 g_S4 [MAXIMG * HWSZ];
__device__ float2 g_ab [MAXIMG * HWSZ];
__device__ float2 g_sab[MAXIMG * HWSZ];

// ---------------------------------------------------------------------------
// Row box-sum via per-row prefix sum in shared memory.
// Block = 256 threads, each owns 4 consecutive elements of a 1024-wide row.
// ---------------------------------------------------------------------------
__device__ __forceinline__ float4 scan_box(float4 e, float* csp, float* wsum, int t)
{
    float s0 = e.x;
    float s1 = s0 + e.y;
    float s2 = s1 + e.z;
    float s3 = s2 + e.w;          // thread-local inclusive sums

    int lane = t & 31;
    int warp = t >> 5;

    float v = s3;
#pragma unroll
    for (int off = 1; off < 32; off <<= 1) {
        float n = __shfl_up_sync(0xffffffffu, v, off);
        if (lane >= off) v += n;
    }
    if (lane == 31) wsum[warp] = v;
    __syncthreads();

    float wb = 0.0f;
#pragma unroll
    for (int w2 = 0; w2 < 7; w2++)
        wb += (w2 < warp) ? wsum[w2] : 0.0f;

    float excl = wb + v - s3;     // sum of all elements before index 4t

    int x = t * 4;
    csp[x + 0] = excl;
    csp[x + 1] = excl + s0;
    csp[x + 2] = excl + s1;
    csp[x + 3] = excl + s2;
    if (t == 255) csp[WW] = excl + s3;
    __syncthreads();

    float4 o;
    o.x = csp[min(x + RAD + 1, WW)] - csp[max(x - RAD, 0)];
    o.y = csp[min(x + RAD + 2, WW)] - csp[max(x + 1 - RAD, 0)];
    o.z = csp[min(x + RAD + 3, WW)] - csp[max(x + 2 - RAD, 0)];
    o.w = csp[min(x + RAD + 4, WW)] - csp[max(x + 3 - RAD, 0)];
    __syncthreads();
    return o;
}

// ---------------------------------------------------------------------------
// Stage 1 horizontal: read I, p; write interleaved row-boxsums S4
// grid = (HH, nimg), block = 256
// ---------------------------------------------------------------------------
__global__ __launch_bounds__(256)
void hpass1(const float* __restrict__ I, const float* __restrict__ P)
{
    __shared__ float csp[WW + 1];
    __shared__ float wsum[8];

    int t = threadIdx.x;
    size_t base = ((size_t)blockIdx.y * HH + blockIdx.x) * WW;
    size_t off  = base + (size_t)t * 4;

    float4 vI = *(const float4*)(I + off);
    float4 vP = *(const float4*)(P + off);

    float4 sI  = scan_box(vI, csp, wsum, t);
    float4 sP  = scan_box(vP, csp, wsum, t);
    float4 ip  = make_float4(vI.x * vP.x, vI.y * vP.y, vI.z * vP.z, vI.w * vP.w);
    float4 sIP = scan_box(ip, csp, wsum, t);
    float4 ii  = make_float4(vI.x * vI.x, vI.y * vI.y, vI.z * vI.z, vI.w * vI.w);
    float4 sII = scan_box(ii, csp, wsum, t);

    g_S4[off + 0] = make_float4(sI.x, sP.x, sIP.x, sII.x);
    g_S4[off + 1] = make_float4(sI.y, sP.y, sIP.y, sII.y);
    g_S4[off + 2] = make_float4(sI.z, sP.z, sIP.z, sII.z);
    g_S4[off + 3] = make_float4(sI.w, sP.w, sIP.w, sII.w);
}

// ---------------------------------------------------------------------------
// Stage 1 vertical: sliding-window column sums of S4, fused a/b computation.
// grid = (WW/256, HH/SEG, nimg), block = 256
// ---------------------------------------------------------------------------
__global__ __launch_bounds__(256)
void vpass1()
{
    int col = blockIdx.x * 256 + threadIdx.x;
    int y0  = blockIdx.y * SEG;
    size_t base = (size_t)blockIdx.z * HWSZ + col;

    const float4* __restrict__ S = g_S4 + base;
    float2*       __restrict__ A = g_ab + base;

    float a0 = 0.f, a1 = 0.f, a2 = 0.f, a3 = 0.f;
    int ys = max(y0 - RAD, 0);
    int ye = min(y0 + RAD, HH - 1);
    for (int y = ys; y <= ye; y++) {
        float4 v = S[(size_t)y * WW];
        a0 += v.x; a1 += v.y; a2 += v.z; a3 += v.w;
    }

    float cx = (float)(min(col + RAD, WW - 1) - max(col - RAD, 0) + 1);
    const float4 z4 = make_float4(0.f, 0.f, 0.f, 0.f);

    for (int yb = y0; yb < y0 + SEG; yb += UNR1) {
        float4 addv[UNR1], subv[UNR1];
#pragma unroll
        for (int u = 0; u < UNR1; u++) {
            int ya = yb + u + RAD + 1;
            int yu = yb + u - RAD;
            addv[u] = (ya < HH)  ? S[(size_t)ya * WW] : z4;
            subv[u] = (yu >= 0)  ? S[(size_t)yu * WW] : z4;
        }
#pragma unroll
        for (int u = 0; u < UNR1; u++) {
            int y = yb + u;
            float cy  = (float)(min(y + RAD, HH - 1) - max(y - RAD, 0) + 1);
            float inv = 1.0f / (cx * cy);

            float mI  = a0 * inv;
            float mP  = a1 * inv;
            float mIP = a2 * inv;
            float mII = a3 * inv;

            float cov = mIP - mI * mP;
            float var = mII - mI * mI;
            float a   = cov / (var + EPSF);
            float b   = mP - a * mI;

            A[(size_t)y * WW] = make_float2(a, b);

            a0 += addv[u].x - subv[u].x;
            a1 += addv[u].y - subv[u].y;
            a2 += addv[u].z - subv[u].z;
            a3 += addv[u].w - subv[u].w;
        }
    }
}

// ---------------------------------------------------------------------------
// Stage 2 horizontal: row-boxsums of (a, b) -> g_sab (interleaved)
// grid = (HH, nimg), block = 256
// ---------------------------------------------------------------------------
__global__ __launch_bounds__(256)
void hpass2()
{
    __shared__ float csp[WW + 1];
    __shared__ float wsum[8];

    int t = threadIdx.x;
    size_t base = ((size_t)blockIdx.y * HH + blockIdx.x) * WW;
    size_t off  = base + (size_t)t * 4;

    // 4 pixels * float2 = 32 contiguous bytes -> two float4 loads
    float4 q0 = *(const float4*)(g_ab + off);       // {a0,b0,a1,b1}
    float4 q1 = *(const float4*)(g_ab + off + 2);   // {a2,b2,a3,b3}

    float4 va = make_float4(q0.x, q0.z, q1.x, q1.z);
    float4 vb = make_float4(q0.y, q0.w, q1.y, q1.w);

    float4 sa = scan_box(va, csp, wsum, t);
    float4 sb = scan_box(vb, csp, wsum, t);

    g_sab[off + 0] = make_float2(sa.x, sb.x);
    g_sab[off + 1] = make_float2(sa.y, sb.y);
    g_sab[off + 2] = make_float2(sa.z, sb.z);
    g_sab[off + 3] = make_float2(sa.w, sb.w);
}

// ---------------------------------------------------------------------------
// Stage 2 vertical: sliding-window column sums of (a,b); final output.
// grid = (WW/256, HH/SEG, nimg), block = 256
// ---------------------------------------------------------------------------
__global__ __launch_bounds__(256)
void vpass2(const float* __restrict__ I, float* __restrict__ out)
{
    int col = blockIdx.x * 256 + threadIdx.x;
    int y0  = blockIdx.y * SEG;
    size_t base = (size_t)blockIdx.z * HWSZ + col;

    const float2* __restrict__ S  = g_sab + base;
    const float*  __restrict__ Ip = I + base;
    float*        __restrict__ O  = out + base;

    float a0 = 0.f, a1 = 0.f;
    int ys = max(y0 - RAD, 0);
    int ye = min(y0 + RAD, HH - 1);
    for (int y = ys; y <= ye; y++) {
        float2 v = S[(size_t)y * WW];
        a0 += v.x; a1 += v.y;
    }

    float cx = (float)(min(col + RAD, WW - 1) - max(col - RAD, 0) + 1);
    const float2 z2 = make_float2(0.f, 0.f);

    for (int yb = y0; yb < y0 + SEG; yb += UNR2) {
        float2 addv[UNR2], subv[UNR2];
        float  iv[UNR2];
#pragma unroll
        for (int u = 0; u < UNR2; u++) {
            int ya = yb + u + RAD + 1;
            int yu = yb + u - RAD;
            addv[u] = (ya < HH) ? S[(size_t)ya * WW] : z2;
            subv[u] = (yu >= 0) ? S[(size_t)yu * WW] : z2;
            iv[u]   = Ip[(size_t)(yb + u) * WW];
        }
#pragma unroll
        for (int u = 0; u < UNR2; u++) {
            int y = yb + u;
            float cy  = (float)(min(y + RAD, HH - 1) - max(y - RAD, 0) + 1);
            float inv = 1.0f / (cx * cy);

            O[(size_t)y * WW] = (a0 * inv) * iv[u] + (a1 * inv);

            a0 += addv[u].x - subv[u].x;
            a1 += addv[u].y - subv[u].y;
        }
    }
}

// ---------------------------------------------------------------------------
extern "C" void kernel_launch(void* const* d_in, const int* in_sizes, int n_in,
                              void* d_out, int out_size)
{
    const float* I = (const float*)d_in[0];
    const float* P = (const float*)d_in[1];
    float* out     = (float*)d_out;

    int nimg = in_sizes[0] / HWSZ;      // B*C images of 1024x1024
    if (nimg > MAXIMG) nimg = MAXIMG;

    dim3 hgrid(HH, nimg);
    dim3 vgrid(WW / 256, HH / SEG, nimg);

    hpass1<<<hgrid, 256>>>(I, P);
    vpass1<<<vgrid, 256>>>();
    hpass2<<<hgrid, 256>>>();
    vpass2<<<vgrid, 256>>>(I, out);
}

// round 3
// speedup vs baseline: 1.5156x; 1.1741x over previous
#include <cuda_runtime.h>
#include <cuda_bf16.h>

#define HH   1024
#define WW   1024
#define RAD  40
#define EPSF 1e-3f
#define MAXIMG 12
#define HWSZ (HH * WW)
#define SEG  128         // rows per thread in vertical sliding passes
#define UNRV 8           // unroll in vertical passes

// ---------------------------------------------------------------------------
// Scratch (static __device__ arrays -- no runtime allocation).
//   g_V4  : vertical box sums of (I, p, I*p, I*I)  -- float4 per pixel
//   g_ab  : (a, b) per pixel                        -- float2
//   g_sab : vertical box sums of (a, b)             -- float2
// ---------------------------------------------------------------------------
__device__ float4 g_V4 [MAXIMG * HWSZ];
__device__ float2 g_ab [MAXIMG * HWSZ];
__device__ float2 g_sab[MAXIMG * HWSZ];

// ---------------------------------------------------------------------------
// Stage 1 vertical: sliding column sums of (I, p, I*p, I*I) from raw inputs.
// grid = (WW/256, HH/SEG, nimg), block = 256
// ---------------------------------------------------------------------------
__global__ __launch_bounds__(256)
void vpassA(const float* __restrict__ I, const float* __restrict__ P)
{
    int col = blockIdx.x * 256 + threadIdx.x;
    int y0  = blockIdx.y * SEG;
    size_t base = (size_t)blockIdx.z * HWSZ + col;

    const float* __restrict__ Ic = I + base;
    const float* __restrict__ Pc = P + base;
    float4* __restrict__ V = g_V4 + base;

    float sI = 0.f, sP = 0.f, sIP = 0.f, sII = 0.f;
    int ys = max(y0 - RAD, 0);
    int ye = min(y0 + RAD, HH - 1);
    for (int y = ys; y <= ye; y++) {
        float i = Ic[(size_t)y * WW];
        float p = Pc[(size_t)y * WW];
        sI += i; sP += p; sIP += i * p; sII += i * i;
    }

    for (int yb = y0; yb < y0 + SEG; yb += UNRV) {
        float ai[UNRV], ap[UNRV], si[UNRV], sp[UNRV];
#pragma unroll
        for (int u = 0; u < UNRV; u++) {
            int ya = yb + u + RAD + 1;
            int yu = yb + u - RAD;
            ai[u] = (ya < HH) ? Ic[(size_t)ya * WW] : 0.f;
            ap[u] = (ya < HH) ? Pc[(size_t)ya * WW] : 0.f;
            si[u] = (yu >= 0) ? Ic[(size_t)yu * WW] : 0.f;
            sp[u] = (yu >= 0) ? Pc[(size_t)yu * WW] : 0.f;
        }
#pragma unroll
        for (int u = 0; u < UNRV; u++) {
            int y = yb + u;
            V[(size_t)y * WW] = make_float4(sI, sP, sIP, sII);
            sI  += ai[u] - si[u];
            sP  += ap[u] - sp[u];
            sIP += ai[u] * ap[u] - si[u] * sp[u];
            sII += ai[u] * ai[u] - si[u] * si[u];
        }
    }
}

// ---------------------------------------------------------------------------
// Stage 1 horizontal: row prefix-scan of V4 (4 quantities merged, 2 syncs),
// box window completes the 2D sum; fused a/b computation.
// grid = (HH, nimg), block = 256
// ---------------------------------------------------------------------------
__global__ __launch_bounds__(256)
void hpassA()
{
    __shared__ float csp[4][WW + 1];
    __shared__ float wsum[4][8];

    int t    = threadIdx.x;
    int lane = t & 31;
    int warp = t >> 5;
    int row  = blockIdx.x;
    size_t base = ((size_t)blockIdx.y * HH + row) * WW;
    size_t off  = base + (size_t)t * 4;

    float4 q0 = g_V4[off + 0];
    float4 q1 = g_V4[off + 1];
    float4 q2 = g_V4[off + 2];
    float4 q3 = g_V4[off + 3];

    float e[4][4] = {
        { q0.x, q1.x, q2.x, q3.x },   // sI
        { q0.y, q1.y, q2.y, q3.y },   // sP
        { q0.z, q1.z, q2.z, q3.z },   // sIP
        { q0.w, q1.w, q2.w, q3.w }    // sII
    };

    float loc[4][4], v[4];
#pragma unroll
    for (int q = 0; q < 4; q++) {
        loc[q][0] = e[q][0];
        loc[q][1] = loc[q][0] + e[q][1];
        loc[q][2] = loc[q][1] + e[q][2];
        loc[q][3] = loc[q][2] + e[q][3];
        v[q] = loc[q][3];
    }

#pragma unroll
    for (int d = 1; d < 32; d <<= 1) {
#pragma unroll
        for (int q = 0; q < 4; q++) {
            float n = __shfl_up_sync(0xffffffffu, v[q], d);
            if (lane >= d) v[q] += n;
        }
    }
    if (lane == 31) {
#pragma unroll
        for (int q = 0; q < 4; q++) wsum[q][warp] = v[q];
    }
    __syncthreads();

    int x = t * 4;
#pragma unroll
    for (int q = 0; q < 4; q++) {
        float wb = 0.f;
#pragma unroll
        for (int w2 = 0; w2 < 7; w2++)
            wb += (w2 < warp) ? wsum[q][w2] : 0.f;
        float excl = wb + v[q] - loc[q][3];
        csp[q][x + 0] = excl;
        csp[q][x + 1] = excl + loc[q][0];
        csp[q][x + 2] = excl + loc[q][1];
        csp[q][x + 3] = excl + loc[q][2];
        if (t == 255) csp[q][WW] = excl + loc[q][3];
    }
    __syncthreads();

    float cy = (float)(min(row + RAD, HH - 1) - max(row - RAD, 0) + 1);

    float2 ab[4];
#pragma unroll
    for (int k = 0; k < 4; k++) {
        int hi = min(x + k + RAD + 1, WW);
        int lo = max(x + k - RAD, 0);
        float bI  = csp[0][hi] - csp[0][lo];
        float bP  = csp[1][hi] - csp[1][lo];
        float bIP = csp[2][hi] - csp[2][lo];
        float bII = csp[3][hi] - csp[3][lo];

        float cx  = (float)(min(x + k + RAD, WW - 1) - max(x + k - RAD, 0) + 1);
        float inv = 1.0f / (cx * cy);

        float mI  = bI  * inv;
        float mP  = bP  * inv;
        float mIP = bIP * inv;
        float mII = bII * inv;

        float cov = mIP - mI * mP;
        float var = mII - mI * mI;
        float a   = cov / (var + EPSF);
        float b   = mP - a * mI;
        ab[k] = make_float2(a, b);
    }

    *(float4*)(g_ab + off)     = make_float4(ab[0].x, ab[0].y, ab[1].x, ab[1].y);
    *(float4*)(g_ab + off + 2) = make_float4(ab[2].x, ab[2].y, ab[3].x, ab[3].y);
}

// ---------------------------------------------------------------------------
// Stage 2 vertical: sliding column sums of (a, b).
// grid = (WW/256, HH/SEG, nimg), block = 256
// ---------------------------------------------------------------------------
__global__ __launch_bounds__(256)
void vpassB()
{
    int col = blockIdx.x * 256 + threadIdx.x;
    int y0  = blockIdx.y * SEG;
    size_t base = (size_t)blockIdx.z * HWSZ + col;

    const float2* __restrict__ A = g_ab + base;
    float2*       __restrict__ S = g_sab + base;

    float sa = 0.f, sb = 0.f;
    int ys = max(y0 - RAD, 0);
    int ye = min(y0 + RAD, HH - 1);
    for (int y = ys; y <= ye; y++) {
        float2 v = A[(size_t)y * WW];
        sa += v.x; sb += v.y;
    }

    const float2 z2 = make_float2(0.f, 0.f);
    for (int yb = y0; yb < y0 + SEG; yb += UNRV) {
        float2 addv[UNRV], subv[UNRV];
#pragma unroll
        for (int u = 0; u < UNRV; u++) {
            int ya = yb + u + RAD + 1;
            int yu = yb + u - RAD;
            addv[u] = (ya < HH) ? A[(size_t)ya * WW] : z2;
            subv[u] = (yu >= 0) ? A[(size_t)yu * WW] : z2;
        }
#pragma unroll
        for (int u = 0; u < UNRV; u++) {
            int y = yb + u;
            S[(size_t)y * WW] = make_float2(sa, sb);
            sa += addv[u].x - subv[u].x;
            sb += addv[u].y - subv[u].y;
        }
    }
}

// ---------------------------------------------------------------------------
// Stage 2 horizontal: row scan of (sum_a, sum_b), box window, final output.
// out = mean_a * I + mean_b
// grid = (HH, nimg), block = 256
// ---------------------------------------------------------------------------
__global__ __launch_bounds__(256)
void hpassB(const float* __restrict__ I, float* __restrict__ out)
{
    __shared__ float csp[2][WW + 1];
    __shared__ float wsum[2][8];

    int t    = threadIdx.x;
    int lane = t & 31;
    int warp = t >> 5;
    int row  = blockIdx.x;
    size_t base = ((size_t)blockIdx.y * HH + row) * WW;
    size_t off  = base + (size_t)t * 4;

    float4 q0 = *(const float4*)(g_sab + off);       // {a0,b0,a1,b1}
    float4 q1 = *(const float4*)(g_sab + off + 2);   // {a2,b2,a3,b3}

    float e[2][4] = {
        { q0.x, q0.z, q1.x, q1.z },   // sum_a
        { q0.y, q0.w, q1.y, q1.w }    // sum_b
    };

    float loc[2][4], v[2];
#pragma unroll
    for (int q = 0; q < 2; q++) {
        loc[q][0] = e[q][0];
        loc[q][1] = loc[q][0] + e[q][1];
        loc[q][2] = loc[q][1] + e[q][2];
        loc[q][3] = loc[q][2] + e[q][3];
        v[q] = loc[q][3];
    }

#pragma unroll
    for (int d = 1; d < 32; d <<= 1) {
#pragma unroll
        for (int q = 0; q < 2; q++) {
            float n = __shfl_up_sync(0xffffffffu, v[q], d);
            if (lane >= d) v[q] += n;
        }
    }
    if (lane == 31) {
#pragma unroll
        for (int q = 0; q < 2; q++) wsum[q][warp] = v[q];
    }
    __syncthreads();

    int x = t * 4;
#pragma unroll
    for (int q = 0; q < 2; q++) {
        float wb = 0.f;
#pragma unroll
        for (int w2 = 0; w2 < 7; w2++)
            wb += (w2 < warp) ? wsum[q][w2] : 0.f;
        float excl = wb + v[q] - loc[q][3];
        csp[q][x + 0] = excl;
        csp[q][x + 1] = excl + loc[q][0];
        csp[q][x + 2] = excl + loc[q][1];
        csp[q][x + 3] = excl + loc[q][2];
        if (t == 255) csp[q][WW] = excl + loc[q][3];
    }
    __syncthreads();

    float cy = (float)(min(row + RAD, HH - 1) - max(row - RAD, 0) + 1);
    float4 vI = *(const float4*)(I + off);
    float iv[4] = { vI.x, vI.y, vI.z, vI.w };

    float4 o;
    float* op = &o.x;
#pragma unroll
    for (int k = 0; k < 4; k++) {
        int hi = min(x + k + RAD + 1, WW);
        int lo = max(x + k - RAD, 0);
        float ba = csp[0][hi] - csp[0][lo];
        float bb = csp[1][hi] - csp[1][lo];
        float cx  = (float)(min(x + k + RAD, WW - 1) - max(x + k - RAD, 0) + 1);
        float inv = 1.0f / (cx * cy);
        op[k] = (ba * inv) * iv[k] + (bb * inv);
    }
    *(float4*)(out + off) = o;
}

// ---------------------------------------------------------------------------
extern "C" void kernel_launch(void* const* d_in, const int* in_sizes, int n_in,
                              void* d_out, int out_size)
{
    const float* I = (const float*)d_in[0];
    const float* P = (const float*)d_in[1];
    float* out     = (float*)d_out;

    int nimg = in_sizes[0] / HWSZ;      // B*C images of 1024x1024
    if (nimg > MAXIMG) nimg = MAXIMG;

    dim3 hgrid(HH, nimg);
    dim3 vgrid(WW / 256, HH / SEG, nimg);

    vpassA<<<vgrid, 256>>>(I, P);
    hpassA<<<hgrid, 256>>>();
    vpassB<<<vgrid, 256>>>();
    hpassB<<<hgrid, 256>>>(I, out);
}

// round 4
// speedup vs baseline: 1.7689x; 1.1671x over previous
#include <cuda_runtime.h>
#include <cuda_bf16.h>

#define HH   1024
#define WW   1024
#define RAD  40
#define EPSF 1e-3f
#define MAXIMG 12
#define HWSZ (HH * WW)
#define SEG  128         // rows per thread in vertical sliding passes
#define UNRV 8           // unroll in vertical passes
#define TPBV 128         // threads per block, vertical passes

#define PADL 40          // left padding (zeros) in csp
#define CSPN 1112        // PADL + 1024 + 48 right padding

// ---------------------------------------------------------------------------
// Scratch (static __device__ arrays -- no runtime allocation).
// ---------------------------------------------------------------------------
__device__ float4 g_V4 [MAXIMG * HWSZ];   // vertical box sums (I, p, I*p, I*I)
__device__ float2 g_ab [MAXIMG * HWSZ];   // (a, b)
__device__ float2 g_sab[MAXIMG * HWSZ];   // vertical box sums (a, b)

// ---------------------------------------------------------------------------
// Stage 1 vertical: sliding column sums of (I, p, I*p, I*I) from raw inputs.
// grid = (WW/TPBV, HH/SEG, nimg), block = TPBV
// ---------------------------------------------------------------------------
__global__ __launch_bounds__(TPBV)
void vpassA(const float* __restrict__ I, const float* __restrict__ P)
{
    int col = blockIdx.x * TPBV + threadIdx.x;
    int y0  = blockIdx.y * SEG;
    size_t base = (size_t)blockIdx.z * HWSZ + col;

    const float* __restrict__ Ic = I + base;
    const float* __restrict__ Pc = P + base;
    float4* __restrict__ V = g_V4 + base;

    float sI = 0.f, sP = 0.f, sIP = 0.f, sII = 0.f;
    int ys = max(y0 - RAD, 0);
    int ye = min(y0 + RAD, HH - 1);
    for (int y = ys; y <= ye; y++) {
        float i = Ic[(size_t)y * WW];
        float p = Pc[(size_t)y * WW];
        sI += i; sP += p; sIP += i * p; sII += i * i;
    }

    for (int yb = y0; yb < y0 + SEG; yb += UNRV) {
        float ai[UNRV], ap[UNRV], si[UNRV], sp[UNRV];
#pragma unroll
        for (int u = 0; u < UNRV; u++) {
            int ya = yb + u + RAD + 1;
            int yu = yb + u - RAD;
            ai[u] = (ya < HH) ? Ic[(size_t)ya * WW] : 0.f;
            ap[u] = (ya < HH) ? Pc[(size_t)ya * WW] : 0.f;
            si[u] = (yu >= 0) ? Ic[(size_t)yu * WW] : 0.f;
            sp[u] = (yu >= 0) ? Pc[(size_t)yu * WW] : 0.f;
        }
#pragma unroll
        for (int u = 0; u < UNRV; u++) {
            int y = yb + u;
            V[(size_t)y * WW] = make_float4(sI, sP, sIP, sII);
            sI  += ai[u] - si[u];
            sP  += ap[u] - sp[u];
            sIP += ai[u] * ap[u] - si[u] * sp[u];
            sII += ai[u] * ai[u] - si[u] * si[u];
        }
    }
}

// ---------------------------------------------------------------------------
// Stage 1 horizontal: row prefix-scan of V4 (4 quantities, padded csp,
// vectorized conflict-free LDS); fused a/b computation.
// grid = (HH, nimg), block = 256
// ---------------------------------------------------------------------------
__global__ __launch_bounds__(256)
void hpassA()
{
    __shared__ float csp[4][CSPN];
    __shared__ float wsum[4][8];

    int t    = threadIdx.x;
    int lane = t & 31;
    int warp = t >> 5;
    int row  = blockIdx.x;
    size_t base = ((size_t)blockIdx.y * HH + row) * WW;
    size_t off  = base + (size_t)t * 4;

    float4 q0 = g_V4[off + 0];
    float4 q1 = g_V4[off + 1];
    float4 q2 = g_V4[off + 2];
    float4 q3 = g_V4[off + 3];

    float e[4][4] = {
        { q0.x, q1.x, q2.x, q3.x },   // sI
        { q0.y, q1.y, q2.y, q3.y },   // sP
        { q0.z, q1.z, q2.z, q3.z },   // sIP
        { q0.w, q1.w, q2.w, q3.w }    // sII
    };

    float loc[4][4], v[4];
#pragma unroll
    for (int q = 0; q < 4; q++) {
        loc[q][0] = e[q][0];
        loc[q][1] = loc[q][0] + e[q][1];
        loc[q][2] = loc[q][1] + e[q][2];
        loc[q][3] = loc[q][2] + e[q][3];
        v[q] = loc[q][3];
    }

#pragma unroll
    for (int d = 1; d < 32; d <<= 1) {
#pragma unroll
        for (int q = 0; q < 4; q++) {
            float n = __shfl_up_sync(0xffffffffu, v[q], d);
            if (lane >= d) v[q] += n;
        }
    }
    if (lane == 31) {
#pragma unroll
        for (int q = 0; q < 4; q++) wsum[q][warp] = v[q];
    }
    __syncthreads();

    int x = t * 4;
#pragma unroll
    for (int q = 0; q < 4; q++) {
        float wb = 0.f;
#pragma unroll
        for (int w2 = 0; w2 < 7; w2++)
            wb += (w2 < warp) ? wsum[q][w2] : 0.f;
        float excl = wb + v[q] - loc[q][3];
        *(float4*)&csp[q][PADL + x] =
            make_float4(excl, excl + loc[q][0], excl + loc[q][1], excl + loc[q][2]);
        if (t < 10)
            *(float4*)&csp[q][t * 4] = make_float4(0.f, 0.f, 0.f, 0.f);
        if (t >= 240 && t < 252) {
            float tot = wsum[q][0] + wsum[q][1] + wsum[q][2] + wsum[q][3]
                      + wsum[q][4] + wsum[q][5] + wsum[q][6] + wsum[q][7];
            *(float4*)&csp[q][PADL + WW + (t - 240) * 4] =
                make_float4(tot, tot, tot, tot);
        }
    }
    __syncthreads();

    float cy = (float)(min(row + RAD, HH - 1) - max(row - RAD, 0) + 1);

    float B[4][4];
#pragma unroll
    for (int q = 0; q < 4; q++) {
        float4 L  = *(const float4*)&csp[q][PADL + x - RAD];        // x-40..x-37
        float4 HA = *(const float4*)&csp[q][PADL + x + RAD];        // x+40..x+43
        float4 HB = *(const float4*)&csp[q][PADL + x + RAD + 4];    // x+44..x+47
        B[q][0] = HA.y - L.x;
        B[q][1] = HA.z - L.y;
        B[q][2] = HA.w - L.z;
        B[q][3] = HB.x - L.w;
    }

    float2 ab[4];
#pragma unroll
    for (int k = 0; k < 4; k++) {
        float cx  = (float)(min(x + k + RAD, WW - 1) - max(x + k - RAD, 0) + 1);
        float inv = 1.0f / (cx * cy);

        float mI  = B[0][k] * inv;
        float mP  = B[1][k] * inv;
        float mIP = B[2][k] * inv;
        float mII = B[3][k] * inv;

        float cov = mIP - mI * mP;
        float var = mII - mI * mI;
        float a   = cov / (var + EPSF);
        float b   = mP - a * mI;
        ab[k] = make_float2(a, b);
    }

    *(float4*)(g_ab + off)     = make_float4(ab[0].x, ab[0].y, ab[1].x, ab[1].y);
    *(float4*)(g_ab + off + 2) = make_float4(ab[2].x, ab[2].y, ab[3].x, ab[3].y);
}

// ---------------------------------------------------------------------------
// Stage 2 vertical: sliding column sums of (a, b).
// grid = (WW/TPBV, HH/SEG, nimg), block = TPBV
// ---------------------------------------------------------------------------
__global__ __launch_bounds__(TPBV)
void vpassB()
{
    int col = blockIdx.x * TPBV + threadIdx.x;
    int y0  = blockIdx.y * SEG;
    size_t base = (size_t)blockIdx.z * HWSZ + col;

    const float2* __restrict__ A = g_ab + base;
    float2*       __restrict__ S = g_sab + base;

    float sa = 0.f, sb = 0.f;
    int ys = max(y0 - RAD, 0);
    int ye = min(y0 + RAD, HH - 1);
    for (int y = ys; y <= ye; y++) {
        float2 v = A[(size_t)y * WW];
        sa += v.x; sb += v.y;
    }

    const float2 z2 = make_float2(0.f, 0.f);
    for (int yb = y0; yb < y0 + SEG; yb += UNRV) {
        float2 addv[UNRV], subv[UNRV];
#pragma unroll
        for (int u = 0; u < UNRV; u++) {
            int ya = yb + u + RAD + 1;
            int yu = yb + u - RAD;
            addv[u] = (ya < HH) ? A[(size_t)ya * WW] : z2;
            subv[u] = (yu >= 0) ? A[(size_t)yu * WW] : z2;
        }
#pragma unroll
        for (int u = 0; u < UNRV; u++) {
            int y = yb + u;
            S[(size_t)y * WW] = make_float2(sa, sb);
            sa += addv[u].x - subv[u].x;
            sb += addv[u].y - subv[u].y;
        }
    }
}

// ---------------------------------------------------------------------------
// Stage 2 horizontal: row scan of (sum_a, sum_b), padded csp, final output.
// out = mean_a * I + mean_b
// grid = (HH, nimg), block = 256
// ---------------------------------------------------------------------------
__global__ __launch_bounds__(256)
void hpassB(const float* __restrict__ I, float* __restrict__ out)
{
    __shared__ float csp[2][CSPN];
    __shared__ float wsum[2][8];

    int t    = threadIdx.x;
    int lane = t & 31;
    int warp = t >> 5;
    int row  = blockIdx.x;
    size_t base = ((size_t)blockIdx.y * HH + row) * WW;
    size_t off  = base + (size_t)t * 4;

    float4 q0 = *(const float4*)(g_sab + off);       // {a0,b0,a1,b1}
    float4 q1 = *(const float4*)(g_sab + off + 2);   // {a2,b2,a3,b3}

    float e[2][4] = {
        { q0.x, q0.z, q1.x, q1.z },   // sum_a
        { q0.y, q0.w, q1.y, q1.w }    // sum_b
    };

    float loc[2][4], v[2];
#pragma unroll
    for (int q = 0; q < 2; q++) {
        loc[q][0] = e[q][0];
        loc[q][1] = loc[q][0] + e[q][1];
        loc[q][2] = loc[q][1] + e[q][2];
        loc[q][3] = loc[q][2] + e[q][3];
        v[q] = loc[q][3];
    }

#pragma unroll
    for (int d = 1; d < 32; d <<= 1) {
#pragma unroll
        for (int q = 0; q < 2; q++) {
            float n = __shfl_up_sync(0xffffffffu, v[q], d);
            if (lane >= d) v[q] += n;
        }
    }
    if (lane == 31) {
#pragma unroll
        for (int q = 0; q < 2; q++) wsum[q][warp] = v[q];
    }
    __syncthreads();

    int x = t * 4;
#pragma unroll
    for (int q = 0; q < 2; q++) {
        float wb = 0.f;
#pragma unroll
        for (int w2 = 0; w2 < 7; w2++)
            wb += (w2 < warp) ? wsum[q][w2] : 0.f;
        float excl = wb + v[q] - loc[q][3];
        *(float4*)&csp[q][PADL + x] =
            make_float4(excl, excl + loc[q][0], excl + loc[q][1], excl + loc[q][2]);
        if (t < 10)
            *(float4*)&csp[q][t * 4] = make_float4(0.f, 0.f, 0.f, 0.f);
        if (t >= 240 && t < 252) {
            float tot = wsum[q][0] + wsum[q][1] + wsum[q][2] + wsum[q][3]
                      + wsum[q][4] + wsum[q][5] + wsum[q][6] + wsum[q][7];
            *(float4*)&csp[q][PADL + WW + (t - 240) * 4] =
                make_float4(tot, tot, tot, tot);
        }
    }
    __syncthreads();

    float cy = (float)(min(row + RAD, HH - 1) - max(row - RAD, 0) + 1);
    float4 vI = *(const float4*)(I + off);
    float iv[4] = { vI.x, vI.y, vI.z, vI.w };

    float B[2][4];
#pragma unroll
    for (int q = 0; q < 2; q++) {
        float4 L  = *(const float4*)&csp[q][PADL + x - RAD];
        float4 HA = *(const float4*)&csp[q][PADL + x + RAD];
        float4 HB = *(const float4*)&csp[q][PADL + x + RAD + 4];
        B[q][0] = HA.y - L.x;
        B[q][1] = HA.z - L.y;
        B[q][2] = HA.w - L.z;
        B[q][3] = HB.x - L.w;
    }

    float4 o;
    float* op = &o.x;
#pragma unroll
    for (int k = 0; k < 4; k++) {
        float cx  = (float)(min(x + k + RAD, WW - 1) - max(x + k - RAD, 0) + 1);
        float inv = 1.0f / (cx * cy);
        op[k] = (B[0][k] * inv) * iv[k] + (B[1][k] * inv);
    }
    *(float4*)(out + off) = o;
}

// ---------------------------------------------------------------------------
extern "C" void kernel_launch(void* const* d_in, const int* in_sizes, int n_in,
                              void* d_out, int out_size)
{
    const float* I = (const float*)d_in[0];
    const float* P = (const float*)d_in[1];
    float* out     = (float*)d_out;

    int nimg = in_sizes[0] / HWSZ;      // B*C images of 1024x1024
    if (nimg > MAXIMG) nimg = MAXIMG;

    dim3 hgrid(HH, nimg);
    dim3 vgrid(WW / TPBV, HH / SEG, nimg);

    vpassA<<<vgrid, TPBV>>>(I, P);
    hpassA<<<hgrid, 256>>>();
    vpassB<<<vgrid, TPBV>>>();
    hpassB<<<hgrid, 256>>>(I, out);
}

// round 5
// speedup vs baseline: 2.0275x; 1.1462x over previous
#include <cuda_runtime.h>
#include <cuda_bf16.h>
#include <cuda_fp16.h>

#define HH   1024
#define WW   1024
#define RAD  40
#define EPSF 1e-3f
#define MAXIMG 12
#define HWSZ (HH * WW)
#define SEG  256         // rows per thread in vertical sliding passes
#define UNRV 8           // unroll in vertical passes
#define TPBV 64          // threads per block, vertical passes

#define PADL 40          // left padding (zeros) in csp
#define CSPN 1112        // PADL + 1024 + 48 right padding

// ---------------------------------------------------------------------------
// Scratch (static __device__ arrays -- no runtime allocation).
// All intermediates stored fp16 (inputs centered at 0 so variance math is
// insensitive to storage rounding).
//   g_V4h : vertical box sums of (I', p', I'p', I'I') -- 2x half2 = 8B/px
//   g_abh : (a, b) as half2                            -- 4B/px
//   g_sabh: vertical box sums of (a, b) as half2       -- 4B/px
// ---------------------------------------------------------------------------
__device__ uint2    g_V4h [MAXIMG * HWSZ];
__device__ unsigned g_abh [MAXIMG * HWSZ];
__device__ unsigned g_sabh[MAXIMG * HWSZ];

static __device__ __forceinline__ unsigned pack2(float a, float b)
{
    __half2 h = __floats2half2_rn(a, b);
    return *reinterpret_cast<unsigned*>(&h);
}
static __device__ __forceinline__ float2 unpack2(unsigned u)
{
    return __half22float2(*reinterpret_cast<__half2*>(&u));
}

// ---------------------------------------------------------------------------
// Stage 1 vertical: sliding column sums of (I', p', I'p', I'I'),  X' = X-0.5
// grid = (WW/TPBV, HH/SEG, nimg), block = TPBV
// ---------------------------------------------------------------------------
__global__ __launch_bounds__(TPBV)
void vpassA(const float* __restrict__ I, const float* __restrict__ P)
{
    int col = blockIdx.x * TPBV + threadIdx.x;
    int y0  = blockIdx.y * SEG;
    size_t base = (size_t)blockIdx.z * HWSZ + col;

    const float* __restrict__ Ic = I + base;
    const float* __restrict__ Pc = P + base;
    uint2* __restrict__ V = g_V4h + base;

    float sI = 0.f, sP = 0.f, sIP = 0.f, sII = 0.f;
    int ys = max(y0 - RAD, 0);
    int ye = min(y0 + RAD, HH - 1);
    for (int y = ys; y <= ye; y++) {
        float i = Ic[(size_t)y * WW] - 0.5f;
        float p = Pc[(size_t)y * WW] - 0.5f;
        sI += i; sP += p; sIP += i * p; sII += i * i;
    }

    for (int yb = y0; yb < y0 + SEG; yb += UNRV) {
        float ai[UNRV], ap[UNRV], si[UNRV], sp[UNRV];
#pragma unroll
        for (int u = 0; u < UNRV; u++) {
            int ya = yb + u + RAD + 1;
            int yu = yb + u - RAD;
            ai[u] = (ya < HH) ? Ic[(size_t)ya * WW] - 0.5f : 0.f;
            ap[u] = (ya < HH) ? Pc[(size_t)ya * WW] - 0.5f : 0.f;
            si[u] = (yu >= 0) ? Ic[(size_t)yu * WW] - 0.5f : 0.f;
            sp[u] = (yu >= 0) ? Pc[(size_t)yu * WW] - 0.5f : 0.f;
        }
#pragma unroll
        for (int u = 0; u < UNRV; u++) {
            int y = yb + u;
            uint2 uu;
            uu.x = pack2(sI, sP);
            uu.y = pack2(sIP, sII);
            V[(size_t)y * WW] = uu;
            sI  += ai[u] - si[u];
            sP  += ap[u] - sp[u];
            sIP += ai[u] * ap[u] - si[u] * sp[u];
            sII += ai[u] * ai[u] - si[u] * si[u];
        }
    }
}

// ---------------------------------------------------------------------------
// Stage 1 horizontal: row prefix-scan of V4h (4 quantities, padded csp,
// vectorized conflict-free LDS); fused a/b computation -> abh.
// grid = (HH, nimg), block = 256
// ---------------------------------------------------------------------------
__global__ __launch_bounds__(256)
void hpassA()
{
    __shared__ float csp[4][CSPN];
    __shared__ float wsum[4][8];

    int t    = threadIdx.x;
    int lane = t & 31;
    int warp = t >> 5;
    int row  = blockIdx.x;
    size_t base = ((size_t)blockIdx.y * HH + row) * WW;
    size_t off  = base + (size_t)t * 4;

    uint4 r0 = *(const uint4*)(g_V4h + off);      // px0: (x,y)  px1: (z,w)
    uint4 r1 = *(const uint4*)(g_V4h + off + 2);  // px2, px3

    float2 p0a = unpack2(r0.x), p0b = unpack2(r0.y);
    float2 p1a = unpack2(r0.z), p1b = unpack2(r0.w);
    float2 p2a = unpack2(r1.x), p2b = unpack2(r1.y);
    float2 p3a = unpack2(r1.z), p3b = unpack2(r1.w);

    float e[4][4] = {
        { p0a.x, p1a.x, p2a.x, p3a.x },   // sI'
        { p0a.y, p1a.y, p2a.y, p3a.y },   // sP'
        { p0b.x, p1b.x, p2b.x, p3b.x },   // sI'P'
        { p0b.y, p1b.y, p2b.y, p3b.y }    // sI'I'
    };

    float loc[4][4], v[4];
#pragma unroll
    for (int q = 0; q < 4; q++) {
        loc[q][0] = e[q][0];
        loc[q][1] = loc[q][0] + e[q][1];
        loc[q][2] = loc[q][1] + e[q][2];
        loc[q][3] = loc[q][2] + e[q][3];
        v[q] = loc[q][3];
    }

#pragma unroll
    for (int d = 1; d < 32; d <<= 1) {
#pragma unroll
        for (int q = 0; q < 4; q++) {
            float n = __shfl_up_sync(0xffffffffu, v[q], d);
            if (lane >= d) v[q] += n;
        }
    }
    if (lane == 31) {
#pragma unroll
        for (int q = 0; q < 4; q++) wsum[q][warp] = v[q];
    }
    __syncthreads();

    int x = t * 4;
#pragma unroll
    for (int q = 0; q < 4; q++) {
        float wb = 0.f;
#pragma unroll
        for (int w2 = 0; w2 < 7; w2++)
            wb += (w2 < warp) ? wsum[q][w2] : 0.f;
        float excl = wb + v[q] - loc[q][3];
        *(float4*)&csp[q][PADL + x] =
            make_float4(excl, excl + loc[q][0], excl + loc[q][1], excl + loc[q][2]);
        if (t < 10)
            *(float4*)&csp[q][t * 4] = make_float4(0.f, 0.f, 0.f, 0.f);
        if (t >= 240 && t < 252) {
            float tot = wsum[q][0] + wsum[q][1] + wsum[q][2] + wsum[q][3]
                      + wsum[q][4] + wsum[q][5] + wsum[q][6] + wsum[q][7];
            *(float4*)&csp[q][PADL + WW + (t - 240) * 4] =
                make_float4(tot, tot, tot, tot);
        }
    }
    __syncthreads();

    float cy = (float)(min(row + RAD, HH - 1) - max(row - RAD, 0) + 1);

    float B[4][4];
#pragma unroll
    for (int q = 0; q < 4; q++) {
        float4 L  = *(const float4*)&csp[q][PADL + x - RAD];
        float4 HA = *(const float4*)&csp[q][PADL + x + RAD];
        float4 HB = *(const float4*)&csp[q][PADL + x + RAD + 4];
        B[q][0] = HA.y - L.x;
        B[q][1] = HA.z - L.y;
        B[q][2] = HA.w - L.z;
        B[q][3] = HB.x - L.w;
    }

    uint4 outv;
    unsigned* ov = &outv.x;
#pragma unroll
    for (int k = 0; k < 4; k++) {
        float cx  = (float)(min(x + k + RAD, WW - 1) - max(x + k - RAD, 0) + 1);
        float inv = 1.0f / (cx * cy);

        float mIc = B[0][k] * inv;         // mean of I'
        float mPc = B[1][k] * inv;         // mean of p'
        float cov = B[2][k] * inv - mIc * mPc;
        float var = B[3][k] * inv - mIc * mIc;
        float a   = cov / (var + EPSF);
        float b   = (mPc + 0.5f) - a * (mIc + 0.5f);
        ov[k] = pack2(a, b);
    }
    *(uint4*)(g_abh + off) = outv;
}

// ---------------------------------------------------------------------------
// Stage 2 vertical: sliding column sums of (a, b) from abh -> sabh.
// grid = (WW/TPBV, HH/SEG, nimg), block = TPBV
// ---------------------------------------------------------------------------
__global__ __launch_bounds__(TPBV)
void vpassB()
{
    int col = blockIdx.x * TPBV + threadIdx.x;
    int y0  = blockIdx.y * SEG;
    size_t base = (size_t)blockIdx.z * HWSZ + col;

    const unsigned* __restrict__ A = g_abh + base;
    unsigned*       __restrict__ S = g_sabh + base;

    float sa = 0.f, sb = 0.f;
    int ys = max(y0 - RAD, 0);
    int ye = min(y0 + RAD, HH - 1);
    for (int y = ys; y <= ye; y++) {
        float2 v = unpack2(A[(size_t)y * WW]);
        sa += v.x; sb += v.y;
    }

    for (int yb = y0; yb < y0 + SEG; yb += UNRV) {
        unsigned addr[UNRV], subr[UNRV];
#pragma unroll
        for (int u = 0; u < UNRV; u++) {
            int ya = yb + u + RAD + 1;
            int yu = yb + u - RAD;
            addr[u] = (ya < HH) ? A[(size_t)ya * WW] : 0u;   // half2(0,0) == 0u
            subr[u] = (yu >= 0) ? A[(size_t)yu * WW] : 0u;
        }
#pragma unroll
        for (int u = 0; u < UNRV; u++) {
            int y = yb + u;
            S[(size_t)y * WW] = pack2(sa, sb);
            float2 av = unpack2(addr[u]);
            float2 sv = unpack2(subr[u]);
            sa += av.x - sv.x;
            sb += av.y - sv.y;
        }
    }
}

// ---------------------------------------------------------------------------
// Stage 2 horizontal: row scan of (sum_a, sum_b), padded csp, final output.
// out = mean_a * I + mean_b
// grid = (HH, nimg), block = 256
// ---------------------------------------------------------------------------
__global__ __launch_bounds__(256)
void hpassB(const float* __restrict__ I, float* __restrict__ out)
{
    __shared__ float csp[2][CSPN];
    __shared__ float wsum[2][8];

    int t    = threadIdx.x;
    int lane = t & 31;
    int warp = t >> 5;
    int row  = blockIdx.x;
    size_t base = ((size_t)blockIdx.y * HH + row) * WW;
    size_t off  = base + (size_t)t * 4;

    uint4 r0 = *(const uint4*)(g_sabh + off);   // 4 px, each half2(a,b)
    float2 s0 = unpack2(r0.x);
    float2 s1 = unpack2(r0.y);
    float2 s2 = unpack2(r0.z);
    float2 s3 = unpack2(r0.w);

    float e[2][4] = {
        { s0.x, s1.x, s2.x, s3.x },   // sum_a
        { s0.y, s1.y, s2.y, s3.y }    // sum_b
    };

    float loc[2][4], v[2];
#pragma unroll
    for (int q = 0; q < 2; q++) {
        loc[q][0] = e[q][0];
        loc[q][1] = loc[q][0] + e[q][1];
        loc[q][2] = loc[q][1] + e[q][2];
        loc[q][3] = loc[q][2] + e[q][3];
        v[q] = loc[q][3];
    }

#pragma unroll
    for (int d = 1; d < 32; d <<= 1) {
#pragma unroll
        for (int q = 0; q < 2; q++) {
            float n = __shfl_up_sync(0xffffffffu, v[q], d);
            if (lane >= d) v[q] += n;
        }
    }
    if (lane == 31) {
#pragma unroll
        for (int q = 0; q < 2; q++) wsum[q][warp] = v[q];
    }
    __syncthreads();

    int x = t * 4;
#pragma unroll
    for (int q = 0; q < 2; q++) {
        float wb = 0.f;
#pragma unroll
        for (int w2 = 0; w2 < 7; w2++)
            wb += (w2 < warp) ? wsum[q][w2] : 0.f;
        float excl = wb + v[q] - loc[q][3];
        *(float4*)&csp[q][PADL + x] =
            make_float4(excl, excl + loc[q][0], excl + loc[q][1], excl + loc[q][2]);
        if (t < 10)
            *(float4*)&csp[q][t * 4] = make_float4(0.f, 0.f, 0.f, 0.f);
        if (t >= 240 && t < 252) {
            float tot = wsum[q][0] + wsum[q][1] + wsum[q][2] + wsum[q][3]
                      + wsum[q][4] + wsum[q][5] + wsum[q][6] + wsum[q][7];
            *(float4*)&csp[q][PADL + WW + (t - 240) * 4] =
                make_float4(tot, tot, tot, tot);
        }
    }
    __syncthreads();

    float cy = (float)(min(row + RAD, HH - 1) - max(row - RAD, 0) + 1);
    float4 vI = *(const float4*)(I + off);
    float iv[4] = { vI.x, vI.y, vI.z, vI.w };

    float B[2][4];
#pragma unroll
    for (int q = 0; q < 2; q++) {
        float4 L  = *(const float4*)&csp[q][PADL + x - RAD];
        float4 HA = *(const float4*)&csp[q][PADL + x + RAD];
        float4 HB = *(const float4*)&csp[q][PADL + x + RAD + 4];
        B[q][0] = HA.y - L.x;
        B[q][1] = HA.z - L.y;
        B[q][2] = HA.w - L.z;
        B[q][3] = HB.x - L.w;
    }

    float4 o;
    float* op = &o.x;
#pragma unroll
    for (int k = 0; k < 4; k++) {
        float cx  = (float)(min(x + k + RAD, WW - 1) - max(x + k - RAD, 0) + 1);
        float inv = 1.0f / (cx * cy);
        op[k] = (B[0][k] * inv) * iv[k] + (B[1][k] * inv);
    }
    *(float4*)(out + off) = o;
}

// ---------------------------------------------------------------------------
extern "C" void kernel_launch(void* const* d_in, const int* in_sizes, int n_in,
                              void* d_out, int out_size)
{
    const float* I = (const float*)d_in[0];
    const float* P = (const float*)d_in[1];
    float* out     = (float*)d_out;

    int nimg = in_sizes[0] / HWSZ;      // B*C images of 1024x1024
    if (nimg > MAXIMG) nimg = MAXIMG;

    dim3 hgrid(HH, nimg);
    dim3 vgrid(WW / TPBV, HH / SEG, nimg);

    vpassA<<<vgrid, TPBV>>>(I, P);
    hpassA<<<hgrid, 256>>>();
    vpassB<<<vgrid, TPBV>>>();
    hpassB<<<hgrid, 256>>>(I, out);
}

// round 6
// speedup vs baseline: 2.0308x; 1.0017x over previous
#include <cuda_runtime.h>
#include <cuda_bf16.h>
#include <cuda_fp16.h>

#define HH   1024
#define WW   1024
#define RAD  40
#define EPSF 1e-3f
#define MAXIMG 12
#define HWSZ (HH * WW)
#define SEG  256         // rows per thread in vertical sliding passes
#define UNRV 8           // unroll in vertical passes
#define TPBV 64          // threads per block, vertical passes

#define PADL 40          // left padding (zeros) in csp
#define CSPN 1112        // PADL + 1024 + 48 right padding

// ---------------------------------------------------------------------------
// Scratch (static __device__ arrays -- no runtime allocation).
// Intermediates fp16 (inputs centered at 0 -> variance math insensitive to
// storage rounding).
// ---------------------------------------------------------------------------
__device__ uint2    g_V4h [MAXIMG * HWSZ];   // vert sums (I',p',I'p',I'I') 8B/px
__device__ unsigned g_abh [MAXIMG * HWSZ];   // (a,b) half2 4B/px
__device__ unsigned g_sabh[MAXIMG * HWSZ];   // vert sums (a,b) half2 4B/px

static __device__ __forceinline__ unsigned pack2(float a, float b)
{
    __half2 h = __floats2half2_rn(a, b);
    return *reinterpret_cast<unsigned*>(&h);
}
static __device__ __forceinline__ float2 unpack2(unsigned u)
{
    return __half22float2(*reinterpret_cast<__half2*>(&u));
}

// ---------------------------------------------------------------------------
// Stage 1 vertical: sliding column sums of (I', p', I'p', I'I'),  X' = X-0.5
// grid = (WW/TPBV, HH/SEG, nimg), block = TPBV
// ---------------------------------------------------------------------------
__global__ __launch_bounds__(TPBV)
void vpassA(const float* __restrict__ I, const float* __restrict__ P)
{
    int col = blockIdx.x * TPBV + threadIdx.x;
    int y0  = blockIdx.y * SEG;
    size_t base = (size_t)blockIdx.z * HWSZ + col;

    const float* __restrict__ Ic = I + base;
    const float* __restrict__ Pc = P + base;
    uint2* __restrict__ V = g_V4h + base;

    float sI = 0.f, sP = 0.f, sIP = 0.f, sII = 0.f;
    int ys = max(y0 - RAD, 0);
    int ye = min(y0 + RAD, HH - 1);
    for (int y = ys; y <= ye; y++) {
        float i = Ic[(size_t)y * WW] - 0.5f;
        float p = Pc[(size_t)y * WW] - 0.5f;
        sI += i; sP += p; sIP += i * p; sII += i * i;
    }

    for (int yb = y0; yb < y0 + SEG; yb += UNRV) {
        float ai[UNRV], ap[UNRV], si[UNRV], sp[UNRV];
#pragma unroll
        for (int u = 0; u < UNRV; u++) {
            int ya = yb + u + RAD + 1;
            int yu = yb + u - RAD;
            ai[u] = (ya < HH) ? Ic[(size_t)ya * WW] - 0.5f : 0.f;
            ap[u] = (ya < HH) ? Pc[(size_t)ya * WW] - 0.5f : 0.f;
            si[u] = (yu >= 0) ? Ic[(size_t)yu * WW] - 0.5f : 0.f;
            sp[u] = (yu >= 0) ? Pc[(size_t)yu * WW] - 0.5f : 0.f;
        }
#pragma unroll
        for (int u = 0; u < UNRV; u++) {
            int y = yb + u;
            uint2 uu;
            uu.x = pack2(sI, sP);
            uu.y = pack2(sIP, sII);
            V[(size_t)y * WW] = uu;
            sI  += ai[u] - si[u];
            sP  += ap[u] - sp[u];
            sIP += ai[u] * ap[u] - si[u] * sp[u];
            sII += ai[u] * ai[u] - si[u] * si[u];
        }
    }
}

// ---------------------------------------------------------------------------
// Stage 1 horizontal: row prefix-scan of V4h (4 quantities), warp-0 block
// offsets, padded csp, conflict-free vectorized LDS; fused a/b -> abh.
// grid = (HH, nimg), block = 256
// ---------------------------------------------------------------------------
__global__ __launch_bounds__(256)
void hpassA()
{
    __shared__ float csp[4][CSPN];
    __shared__ float wsum[4][8];
    __shared__ float woff[4][8];
    __shared__ float stot[4];

    int t    = threadIdx.x;
    int lane = t & 31;
    int warp = t >> 5;
    int row  = blockIdx.x;
    size_t base = ((size_t)blockIdx.y * HH + row) * WW;
    size_t off  = base + (size_t)t * 4;

    uint4 r0 = *(const uint4*)(g_V4h + off);
    uint4 r1 = *(const uint4*)(g_V4h + off + 2);

    float2 p0a = unpack2(r0.x), p0b = unpack2(r0.y);
    float2 p1a = unpack2(r0.z), p1b = unpack2(r0.w);
    float2 p2a = unpack2(r1.x), p2b = unpack2(r1.y);
    float2 p3a = unpack2(r1.z), p3b = unpack2(r1.w);

    float e[4][4] = {
        { p0a.x, p1a.x, p2a.x, p3a.x },   // sI'
        { p0a.y, p1a.y, p2a.y, p3a.y },   // sP'
        { p0b.x, p1b.x, p2b.x, p3b.x },   // sI'P'
        { p0b.y, p1b.y, p2b.y, p3b.y }    // sI'I'
    };

    float loc[4][4], v[4];
#pragma unroll
    for (int q = 0; q < 4; q++) {
        loc[q][0] = e[q][0];
        loc[q][1] = loc[q][0] + e[q][1];
        loc[q][2] = loc[q][1] + e[q][2];
        loc[q][3] = loc[q][2] + e[q][3];
        v[q] = loc[q][3];
    }

#pragma unroll
    for (int d = 1; d < 32; d <<= 1) {
#pragma unroll
        for (int q = 0; q < 4; q++) {
            float n = __shfl_up_sync(0xffffffffu, v[q], d);
            if (lane >= d) v[q] += n;
        }
    }
    if (lane == 31) {
#pragma unroll
        for (int q = 0; q < 4; q++) wsum[q][warp] = v[q];
    }
    __syncthreads();

    // warp 0: segmented scan of 4 quantities x 8 warp totals in one pass
    if (warp == 0) {
        int q = lane >> 3;    // 0..3
        int w = lane & 7;
        float vv = wsum[q][w];
        float orig = vv;
#pragma unroll
        for (int d = 1; d < 8; d <<= 1) {
            float n = __shfl_up_sync(0xffffffffu, vv, d, 8);
            if (w >= d) vv += n;
        }
        woff[q][w] = vv - orig;
        if (w == 7) stot[q] = vv;
    }
    __syncthreads();

    int x = t * 4;
#pragma unroll
    for (int q = 0; q < 4; q++) {
        float excl = woff[q][warp] + v[q] - loc[q][3];
        *(float4*)&csp[q][PADL + x] =
            make_float4(excl, excl + loc[q][0], excl + loc[q][1], excl + loc[q][2]);
        if (t < 10)
            *(float4*)&csp[q][t * 4] = make_float4(0.f, 0.f, 0.f, 0.f);
        if (t >= 240 && t < 252) {
            float tot = stot[q];
            *(float4*)&csp[q][PADL + WW + (t - 240) * 4] =
                make_float4(tot, tot, tot, tot);
        }
    }
    __syncthreads();

    float cy = (float)(min(row + RAD, HH - 1) - max(row - RAD, 0) + 1);

    float B[4][4];
#pragma unroll
    for (int q = 0; q < 4; q++) {
        float4 L  = *(const float4*)&csp[q][PADL + x - RAD];
        float4 HA = *(const float4*)&csp[q][PADL + x + RAD];
        float4 HB = *(const float4*)&csp[q][PADL + x + RAD + 4];
        B[q][0] = HA.y - L.x;
        B[q][1] = HA.z - L.y;
        B[q][2] = HA.w - L.z;
        B[q][3] = HB.x - L.w;
    }

    uint4 outv;
    unsigned* ov = &outv.x;
#pragma unroll
    for (int k = 0; k < 4; k++) {
        float cx  = (float)(min(x + k + RAD, WW - 1) - max(x + k - RAD, 0) + 1);
        float inv = 1.0f / (cx * cy);

        float mIc = B[0][k] * inv;
        float mPc = B[1][k] * inv;
        float cov = B[2][k] * inv - mIc * mPc;
        float var = B[3][k] * inv - mIc * mIc;
        float a   = cov / (var + EPSF);
        float b   = (mPc + 0.5f) - a * (mIc + 0.5f);
        ov[k] = pack2(a, b);
    }
    *(uint4*)(g_abh + off) = outv;
}

// ---------------------------------------------------------------------------
// Stage 2 vertical: sliding column sums of (a, b) from abh -> sabh.
// grid = (WW/TPBV, HH/SEG, nimg), block = TPBV
// ---------------------------------------------------------------------------
__global__ __launch_bounds__(TPBV)
void vpassB()
{
    int col = blockIdx.x * TPBV + threadIdx.x;
    int y0  = blockIdx.y * SEG;
    size_t base = (size_t)blockIdx.z * HWSZ + col;

    const unsigned* __restrict__ A = g_abh + base;
    unsigned*       __restrict__ S = g_sabh + base;

    float sa = 0.f, sb = 0.f;
    int ys = max(y0 - RAD, 0);
    int ye = min(y0 + RAD, HH - 1);
    for (int y = ys; y <= ye; y++) {
        float2 v = unpack2(A[(size_t)y * WW]);
        sa += v.x; sb += v.y;
    }

    for (int yb = y0; yb < y0 + SEG; yb += UNRV) {
        unsigned addr[UNRV], subr[UNRV];
#pragma unroll
        for (int u = 0; u < UNRV; u++) {
            int ya = yb + u + RAD + 1;
            int yu = yb + u - RAD;
            addr[u] = (ya < HH) ? A[(size_t)ya * WW] : 0u;
            subr[u] = (yu >= 0) ? A[(size_t)yu * WW] : 0u;
        }
#pragma unroll
        for (int u = 0; u < UNRV; u++) {
            int y = yb + u;
            S[(size_t)y * WW] = pack2(sa, sb);
            float2 av = unpack2(addr[u]);
            float2 sv = unpack2(subr[u]);
            sa += av.x - sv.x;
            sb += av.y - sv.y;
        }
    }
}

// ---------------------------------------------------------------------------
// Stage 2 horizontal: row scan of (sum_a, sum_b), warp-0 offsets, padded
// csp, final output:  out = mean_a * I + mean_b
// grid = (HH, nimg), block = 256
// ---------------------------------------------------------------------------
__global__ __launch_bounds__(256)
void hpassB(const float* __restrict__ I, float* __restrict__ out)
{
    __shared__ float csp[2][CSPN];
    __shared__ float wsum[4][8];      // padded to 4 rows for warp-0 scan
    __shared__ float woff[4][8];
    __shared__ float stot[4];

    int t    = threadIdx.x;
    int lane = t & 31;
    int warp = t >> 5;
    int row  = blockIdx.x;
    size_t base = ((size_t)blockIdx.y * HH + row) * WW;
    size_t off  = base + (size_t)t * 4;

    uint4 r0 = *(const uint4*)(g_sabh + off);
    float2 s0 = unpack2(r0.x);
    float2 s1 = unpack2(r0.y);
    float2 s2 = unpack2(r0.z);
    float2 s3 = unpack2(r0.w);

    float e[2][4] = {
        { s0.x, s1.x, s2.x, s3.x },   // sum_a
        { s0.y, s1.y, s2.y, s3.y }    // sum_b
    };

    float loc[2][4], v[2];
#pragma unroll
    for (int q = 0; q < 2; q++) {
        loc[q][0] = e[q][0];
        loc[q][1] = loc[q][0] + e[q][1];
        loc[q][2] = loc[q][1] + e[q][2];
        loc[q][3] = loc[q][2] + e[q][3];
        v[q] = loc[q][3];
    }

#pragma unroll
    for (int d = 1; d < 32; d <<= 1) {
#pragma unroll
        for (int q = 0; q < 2; q++) {
            float n = __shfl_up_sync(0xffffffffu, v[q], d);
            if (lane >= d) v[q] += n;
        }
    }
    if (lane == 31) {
#pragma unroll
        for (int q = 0; q < 2; q++) wsum[q][warp] = v[q];
    }
    __syncthreads();

    if (warp == 0) {
        int q = lane >> 3;    // 0..3 (q=2,3 scan garbage, discarded)
        int w = lane & 7;
        float vv = wsum[q][w];
        float orig = vv;
#pragma unroll
        for (int d = 1; d < 8; d <<= 1) {
            float n = __shfl_up_sync(0xffffffffu, vv, d, 8);
            if (w >= d) vv += n;
        }
        if (q < 2) {
            woff[q][w] = vv - orig;
            if (w == 7) stot[q] = vv;
        }
    }
    __syncthreads();

    int x = t * 4;
#pragma unroll
    for (int q = 0; q < 2; q++) {
        float excl = woff[q][warp] + v[q] - loc[q][3];
        *(float4*)&csp[q][PADL + x] =
            make_float4(excl, excl + loc[q][0], excl + loc[q][1], excl + loc[q][2]);
        if (t < 10)
            *(float4*)&csp[q][t * 4] = make_float4(0.f, 0.f, 0.f, 0.f);
        if (t >= 240 && t < 252) {
            float tot = stot[q];
            *(float4*)&csp[q][PADL + WW + (t - 240) * 4] =
                make_float4(tot, tot, tot, tot);
        }
    }
    __syncthreads();

    float cy = (float)(min(row + RAD, HH - 1) - max(row - RAD, 0) + 1);
    float4 vI = *(const float4*)(I + off);
    float iv[4] = { vI.x, vI.y, vI.z, vI.w };

    float B[2][4];
#pragma unroll
    for (int q = 0; q < 2; q++) {
        float4 L  = *(const float4*)&csp[q][PADL + x - RAD];
        float4 HA = *(const float4*)&csp[q][PADL + x + RAD];
        float4 HB = *(const float4*)&csp[q][PADL + x + RAD + 4];
        B[q][0] = HA.y - L.x;
        B[q][1] = HA.z - L.y;
        B[q][2] = HA.w - L.z;
        B[q][3] = HB.x - L.w;
    }

    float4 o;
    float* op = &o.x;
#pragma unroll
    for (int k = 0; k < 4; k++) {
        float cx  = (float)(min(x + k + RAD, WW - 1) - max(x + k - RAD, 0) + 1);
        float inv = 1.0f / (cx * cy);
        op[k] = (B[0][k] * inv) * iv[k] + (B[1][k] * inv);
    }
    *(float4*)(out + off) = o;
}

// ---------------------------------------------------------------------------
extern "C" void kernel_launch(void* const* d_in, const int* in_sizes, int n_in,
                              void* d_out, int out_size)
{
    const float* I = (const float*)d_in[0];
    const float* P = (const float*)d_in[1];
    float* out     = (float*)d_out;

    int nimg = in_sizes[0] / HWSZ;      // B*C images of 1024x1024
    if (nimg > MAXIMG) nimg = MAXIMG;

    dim3 hgrid(HH, nimg);
    dim3 vgrid(WW / TPBV, HH / SEG, nimg);

    vpassA<<<vgrid, TPBV>>>(I, P);
    hpassA<<<hgrid, 256>>>();
    vpassB<<<vgrid, TPBV>>>();
    hpassB<<<hgrid, 256>>>(I, out);
}